// round 8
// baseline (speedup 1.0000x reference)
#include <cuda_runtime.h>

// Problem constants (match reference)
#define NVX 200
#define NVY 200
#define NVZ 16
#define N_VOX (NVX * NVY * NVZ)      // 640000
#define FEAT_DIM 17
#define VOXEL 0.4f

#define TILE_W 8                      // 8x8 columns per tile
#define NT_X 25
#define NT_Y 25
#define N_TILES (NT_X * NT_Y)        // 625
#define MAXG 16384

#define CAND_CHUNK 128
#define MAX_ACC 1024
#define CELLS_PER_TILE (TILE_W * TILE_W * NVZ)   // 1024
#define ACC_STRIDE 20                             // 17 feats + dens + inv + pad

// ---------------------------------------------------------------------------
// Device scratch (static, no allocation)
// ---------------------------------------------------------------------------
__device__ float g_par[(size_t)MAXG * 28];   // per-gaussian derived params
__device__ int   g_screen[MAXG];             // packed {mix, miy, miz, rad}
__device__ int   g_cnt[N_TILES];
__device__ int   g_off[N_TILES + 1];
__device__ int   g_cur[N_TILES];
__device__ int   g_list[MAXG];

// ---------------------------------------------------------------------------
// Zero tile counters
// ---------------------------------------------------------------------------
__global__ void zero_cnt_kernel() {
    int t = blockIdx.x * blockDim.x + threadIdx.x;
    if (t < N_TILES) g_cnt[t] = 0;
}

// ---------------------------------------------------------------------------
// Prep: per-gaussian derived params + tile count
// ---------------------------------------------------------------------------
__global__ void prep_kernel(
    const float* __restrict__ means,
    const float* __restrict__ opac,
    const float* __restrict__ scales,
    const float* __restrict__ rots,
    const float* __restrict__ feats,
    int n)
{
    int g = blockIdx.x * blockDim.x + threadIdx.x;
    if (g >= n) return;

    float mx = means[3*g+0], my = means[3*g+1], mz = means[3*g+2];
    float op = opac[g];
    float sx = scales[3*g+0], sy = scales[3*g+1], sz = scales[3*g+2];
    float q0 = rots[4*g+0], q1 = rots[4*g+1], q2 = rots[4*g+2], q3 = rots[4*g+3];

    float qn = rsqrtf(q0*q0 + q1*q1 + q2*q2 + q3*q3 + 1e-8f);
    float r = q0*qn, x = q1*qn, y = q2*qn, z = q3*qn;

    float R00 = 1.f - 2.f*(y*y + z*z);
    float R01 = 2.f*(x*y - r*z);
    float R02 = 2.f*(x*z + r*y);
    float R10 = 2.f*(x*y + r*z);
    float R11 = 1.f - 2.f*(x*x + z*z);
    float R12 = 2.f*(y*z - r*x);
    float R20 = 2.f*(x*z - r*y);
    float R21 = 2.f*(y*z + r*x);
    float R22 = 1.f - 2.f*(x*x + y*y);

    // Cov = R^T diag(s^2) R (R orthogonal)  =>  CovInv = R^T diag(1/s^2) R
    float i0 = 1.f/(sx*sx), i1 = 1.f/(sy*sy), i2 = 1.f/(sz*sz);

    float* P = g_par + (size_t)g * 28;
    P[0] = mx; P[1] = my; P[2] = mz; P[3] = op;
    P[4] = R00*R00*i0 + R10*R10*i1 + R20*R20*i2;   // cxx
    P[5] = R01*R01*i0 + R11*R11*i1 + R21*R21*i2;   // cyy
    P[6] = R02*R02*i0 + R12*R12*i1 + R22*R22*i2;   // czz
    P[7] = R00*R01*i0 + R10*R11*i1 + R20*R21*i2;   // cxy
    P[8] = R01*R02*i0 + R11*R12*i1 + R21*R22*i2;   // cyz
    P[9] = R00*R02*i0 + R10*R12*i1 + R20*R22*i2;   // cxz
    #pragma unroll
    for (int k = 0; k < FEAT_DIM; k++) P[10+k] = feats[FEAT_DIM*g + k];

    float smax = fmaxf(sx, fmaxf(sy, sz));
    int rad = (int)ceilf(smax * 3.0f / VOXEL);
    rad = max(1, min(3, rad));          // offsets limited to +-3 in reference

    int mix = (int)floorf((mx + 40.f) / VOXEL);
    int miy = (int)floorf((my + 40.f) / VOXEL);
    int miz = (int)floorf((mz +  1.f) / VOXEL);

    int sw = (mix & 255) | ((miy & 255) << 8) | ((miz & 255) << 16) | (rad << 24);
    P[27] = __int_as_float(sw);
    g_screen[g] = sw;

    int tx = min(max(mix, 0), NVX-1) >> 3;
    int ty = min(max(miy, 0), NVY-1) >> 3;
    atomicAdd(&g_cnt[tx * NT_Y + ty], 1);
}

// ---------------------------------------------------------------------------
// Scan: exclusive prefix over 625 tile counts (single block)
// ---------------------------------------------------------------------------
__global__ void scan_kernel() {
    __shared__ int s[1024];
    int t = threadIdx.x;
    int c = (t < N_TILES) ? g_cnt[t] : 0;
    s[t] = c;
    __syncthreads();
    for (int d = 1; d < 1024; d <<= 1) {
        int v = (t >= d) ? s[t - d] : 0;
        __syncthreads();
        s[t] += v;
        __syncthreads();
    }
    if (t < N_TILES) {
        g_off[t + 1] = s[t];
        g_cur[t]     = s[t] - c;   // exclusive
        if (t == 0) g_off[0] = 0;
    }
}

// ---------------------------------------------------------------------------
// Scatter gaussians into tile lists
// ---------------------------------------------------------------------------
__global__ void scatter_kernel(int n) {
    int g = blockIdx.x * blockDim.x + threadIdx.x;
    if (g >= n) return;
    int sw = g_screen[g];
    int tx = min(max(sw & 255, 0), NVX-1) >> 3;
    int ty = min(max((sw >> 8) & 255, 0), NVY-1) >> 3;
    int pos = atomicAdd(&g_cur[tx * NT_Y + ty], 1);
    g_list[pos] = g;
}

// ---------------------------------------------------------------------------
// Gather: one CTA per 8x8-column tile, smem accumulation, direct output.
// Dynamic smem: acc[1024*20] | par[128*28] | idx[1024]
// ---------------------------------------------------------------------------
#define SMEM_ACC_F  (CELLS_PER_TILE * ACC_STRIDE)      // 20480 floats
#define SMEM_PAR_F  (CAND_CHUNK * 28)                  // 3584 floats
#define SMEM_BYTES  ((SMEM_ACC_F + SMEM_PAR_F) * 4 + MAX_ACC * 4)  // 100352 B

__global__ void __launch_bounds__(256) gather_kernel(float* __restrict__ out) {
    extern __shared__ float smem[];
    float* s_acc = smem;
    float* s_par = smem + SMEM_ACC_F;
    int*   s_idx = (int*)(smem + SMEM_ACC_F + SMEM_PAR_F);
    __shared__ int s_nacc;

    int tid = threadIdx.x;
    int tileId = blockIdx.x;
    int tx = tileId / NT_Y, ty = tileId % NT_Y;
    int X0 = tx * TILE_W, Y0 = ty * TILE_W;

    for (int i = tid; i < SMEM_ACC_F; i += 256) s_acc[i] = 0.f;
    if (tid == 0) s_nacc = 0;
    __syncthreads();

    // ---- Phase A: screen candidates from the 3x3 tile neighborhood ----
    #pragma unroll 1
    for (int dtx = -1; dtx <= 1; dtx++) {
        int ntx = tx + dtx;
        if ((unsigned)ntx >= (unsigned)NT_X) continue;
        #pragma unroll 1
        for (int dty = -1; dty <= 1; dty++) {
            int nty = ty + dty;
            if ((unsigned)nty >= (unsigned)NT_Y) continue;
            int t = ntx * NT_Y + nty;
            int st = g_off[t], en = g_off[t + 1];
            for (int b = st + tid; b < en; b += 256) {
                int g  = g_list[b];
                int sw = g_screen[g];
                int mix = sw & 255, miy = (sw >> 8) & 255, rad = (sw >> 24) & 255;
                if (mix + rad < X0 || mix - rad > X0 + TILE_W - 1) continue;
                if (miy + rad < Y0 || miy - rad > Y0 + TILE_W - 1) continue;
                int p = atomicAdd(&s_nacc, 1);
                if (p < MAX_ACC) s_idx[p] = g;
            }
        }
    }
    __syncthreads();
    int nacc = min(s_nacc, MAX_ACC);

    // ---- Phase B: process accepted candidates in chunks ----
    for (int c0 = 0; c0 < nacc; c0 += CAND_CHUNK) {
        int clen = min(CAND_CHUNK, nacc - c0);
        for (int i = tid; i < clen * 28; i += 256) {
            int k = i / 28, r = i - k * 28;
            s_par[i] = g_par[(size_t)s_idx[c0 + k] * 28 + r];
        }
        __syncthreads();

        for (int k = 0; k < clen; k++) {
            const float* P = s_par + k * 28;
            int sw  = __float_as_int(P[27]);
            int mix = sw & 255, miy = (sw >> 8) & 255;
            int miz = (sw >> 16) & 255, rad = (sw >> 24) & 255;
            int x0 = max(X0, mix - rad), x1 = min(X0 + TILE_W - 1, mix + rad);
            int y0 = max(Y0, miy - rad), y1 = min(Y0 + TILE_W - 1, miy + rad);
            int z0 = max(0,  miz - rad), z1 = min(NVZ - 1, miz + rad);
            int ny = y1 - y0 + 1, nz = z1 - z0 + 1;
            int ncell = (x1 - x0 + 1) * ny * nz;

            float fnz = (float)nz, fny = (float)ny;
            for (int tcell = tid; tcell < ncell; tcell += 256) {
                // tcell -> (dx_i, dy_i, dz_i); exact fp32 div of small ints
                int tq = (int)((float)tcell / fnz);
                int dz = tcell - tq * nz;
                int qy = (int)((float)tq / fny);
                int dy = tq - qy * ny;
                int ix = x0 + qy, iy = y0 + dy, iz = z0 + dz;

                float ddx = P[0] - fmaf((float)ix, VOXEL, -39.8f);
                float ddy = P[1] - fmaf((float)iy, VOXEL, -39.8f);
                float ddz = P[2] - fmaf((float)iz, VOXEL, -0.8f);

                float pw = -0.5f * (P[4]*ddx*ddx + P[5]*ddy*ddy + P[6]*ddz*ddz)
                                 - (P[7]*ddx*ddy + P[8]*ddy*ddz + P[9]*ddx*ddz);
                float c = P[3] * __expf(pw);

                int cell = ((ix - X0) * TILE_W + (iy - Y0)) * NVZ + iz;
                float* a = s_acc + cell * ACC_STRIDE;

                float4 v0 = *(float4*)(a);
                v0.x += c*P[10]; v0.y += c*P[11]; v0.z += c*P[12]; v0.w += c*P[13];
                *(float4*)(a) = v0;
                float4 v1 = *(float4*)(a + 4);
                v1.x += c*P[14]; v1.y += c*P[15]; v1.z += c*P[16]; v1.w += c*P[17];
                *(float4*)(a + 4) = v1;
                float4 v2 = *(float4*)(a + 8);
                v2.x += c*P[18]; v2.y += c*P[19]; v2.z += c*P[20]; v2.w += c*P[21];
                *(float4*)(a + 8) = v2;
                float4 v3 = *(float4*)(a + 12);
                v3.x += c*P[22]; v3.y += c*P[23]; v3.z += c*P[24]; v3.w += c*P[25];
                *(float4*)(a + 12) = v3;
                float2 v4 = *(float2*)(a + 16);
                v4.x += c*P[26]; v4.y += c;
                *(float2*)(a + 16) = v4;
            }
            __syncthreads();   // RMW ownership changes between candidates
        }
    }

    // ---- Writeout: density + normalized features, straight to d_out ----
    for (int cell = tid; cell < CELLS_PER_TILE; cell += 256) {
        float d = s_acc[cell * ACC_STRIDE + 17];
        s_acc[cell * ACC_STRIDE + 18] = 1.f / fmaxf(d, 1e-6f);
        int cx = cell >> 7, cy = (cell >> 4) & 7, iz = cell & 15;
        int v = ((X0 + cx) * NVY + (Y0 + cy)) * NVZ + iz;
        out[v] = d;
    }
    __syncthreads();
    for (int i = tid; i < CELLS_PER_TILE * FEAT_DIM; i += 256) {
        int cell = i / FEAT_DIM, k = i - cell * FEAT_DIM;
        int cx = cell >> 7, cy = (cell >> 4) & 7, iz = cell & 15;
        int v = ((X0 + cx) * NVY + (Y0 + cy)) * NVZ + iz;
        out[N_VOX + (size_t)v * FEAT_DIM + k] =
            s_acc[cell * ACC_STRIDE + k] * s_acc[cell * ACC_STRIDE + 18];
    }
}

// ---------------------------------------------------------------------------
// Launch
// ---------------------------------------------------------------------------
extern "C" void kernel_launch(void* const* d_in, const int* in_sizes, int n_in,
                              void* d_out, int out_size) {
    const float* means  = (const float*)d_in[0];
    const float* opac   = (const float*)d_in[1];
    const float* scales = (const float*)d_in[2];
    const float* rots   = (const float*)d_in[3];
    const float* feats  = (const float*)d_in[4];
    int n = in_sizes[1];              // opacities: one per gaussian
    if (n > MAXG) n = MAXG;

    // Opt-in to >48KB dynamic smem (idempotent; first call is outside capture)
    cudaFuncSetAttribute(gather_kernel,
                         cudaFuncAttributeMaxDynamicSharedMemorySize, SMEM_BYTES);

    zero_cnt_kernel<<<(N_TILES + 255) / 256, 256>>>();
    prep_kernel<<<(n + 255) / 256, 256>>>(means, opac, scales, rots, feats, n);
    scan_kernel<<<1, 1024>>>();
    scatter_kernel<<<(n + 255) / 256, 256>>>(n);
    gather_kernel<<<N_TILES, 256, SMEM_BYTES>>>((float*)d_out);
}

// round 9
// speedup vs baseline: 1.6180x; 1.6180x over previous
#include <cuda_runtime.h>

// Problem constants (match reference)
#define NVX 200
#define NVY 200
#define NVZ 16
#define N_VOX (NVX * NVY * NVZ)      // 640000
#define FEAT_DIM 17
#define VOXEL 0.4f

#define TILE_W 4                      // 4x4 columns per tile
#define NT 50                         // 200/4 tiles per axis
#define N_TILES (NT * NT)            // 2500
#define MAXG 16384
#define LIST_CAP 131072

// ---------------------------------------------------------------------------
// Device scratch (static, no allocation)
// Param row: 8 float4 = 32 floats per gaussian:
//   [0] mx,my,mz,op   [1] cxx,cyy,czz,cxy   [2] cyz,cxz,sw,pad
//   [3..6] f0..f15    [7] f16, 1.0, pad, pad
// Feature PAIRS at float offsets (12+2k,13+2k) -> 9 x u64 for fma.rn.f32x2;
// pair 8 = (f16, 1.0) so density (sum of c) accumulates in the high half.
// ---------------------------------------------------------------------------
__device__ float4 g_par[(size_t)MAXG * 8];
__device__ int    g_screen[MAXG];            // packed {mix, miy, miz, rad}
__device__ int    g_cnt[N_TILES];
__device__ int    g_off[N_TILES + 1];
__device__ int    g_cur[N_TILES];
__device__ int    g_list[LIST_CAP];

// ---------------------------------------------------------------------------
__global__ void zero_cnt_kernel() {
    int t = blockIdx.x * blockDim.x + threadIdx.x;
    if (t < N_TILES) g_cnt[t] = 0;
}

// ---------------------------------------------------------------------------
// Prep: derived params + count into every tile the footprint overlaps
// ---------------------------------------------------------------------------
__global__ void prep_kernel(
    const float* __restrict__ means,
    const float* __restrict__ opac,
    const float* __restrict__ scales,
    const float* __restrict__ rots,
    const float* __restrict__ feats,
    int n)
{
    int g = blockIdx.x * blockDim.x + threadIdx.x;
    if (g >= n) return;

    float mx = means[3*g+0], my = means[3*g+1], mz = means[3*g+2];
    float op = opac[g];
    float sx = scales[3*g+0], sy = scales[3*g+1], sz = scales[3*g+2];
    float q0 = rots[4*g+0], q1 = rots[4*g+1], q2 = rots[4*g+2], q3 = rots[4*g+3];

    float qn = rsqrtf(q0*q0 + q1*q1 + q2*q2 + q3*q3 + 1e-8f);
    float r = q0*qn, x = q1*qn, y = q2*qn, z = q3*qn;

    float R00 = 1.f - 2.f*(y*y + z*z);
    float R01 = 2.f*(x*y - r*z);
    float R02 = 2.f*(x*z + r*y);
    float R10 = 2.f*(x*y + r*z);
    float R11 = 1.f - 2.f*(x*x + z*z);
    float R12 = 2.f*(y*z - r*x);
    float R20 = 2.f*(x*z - r*y);
    float R21 = 2.f*(y*z + r*x);
    float R22 = 1.f - 2.f*(x*x + y*y);

    // Cov = R^T diag(s^2) R (R orthogonal)  =>  CovInv = R^T diag(1/s^2) R
    float i0 = 1.f/(sx*sx), i1 = 1.f/(sy*sy), i2 = 1.f/(sz*sz);

    float cxx = R00*R00*i0 + R10*R10*i1 + R20*R20*i2;
    float cyy = R01*R01*i0 + R11*R11*i1 + R21*R21*i2;
    float czz = R02*R02*i0 + R12*R12*i1 + R22*R22*i2;
    float cxy = R00*R01*i0 + R10*R11*i1 + R20*R21*i2;
    float cyz = R01*R02*i0 + R11*R12*i1 + R21*R22*i2;
    float cxz = R00*R02*i0 + R10*R12*i1 + R20*R22*i2;

    float smax = fmaxf(sx, fmaxf(sy, sz));
    int rad = (int)ceilf(smax * 3.0f / VOXEL);
    rad = max(1, min(3, rad));          // offsets limited to +-3 in reference

    int mix = (int)floorf((mx + 40.f) / VOXEL);
    int miy = (int)floorf((my + 40.f) / VOXEL);
    int miz = (int)floorf((mz +  1.f) / VOXEL);

    int sw = (mix & 255) | ((miy & 255) << 8) | ((miz & 255) << 16) | (rad << 24);
    g_screen[g] = sw;

    float4* P = g_par + (size_t)g * 8;
    P[0] = make_float4(mx, my, mz, op);
    P[1] = make_float4(cxx, cyy, czz, cxy);
    P[2] = make_float4(cyz, cxz, __int_as_float(sw), 0.f);
    const float* f = feats + (size_t)FEAT_DIM * g;
    P[3] = make_float4(f[0],  f[1],  f[2],  f[3]);
    P[4] = make_float4(f[4],  f[5],  f[6],  f[7]);
    P[5] = make_float4(f[8],  f[9],  f[10], f[11]);
    P[6] = make_float4(f[12], f[13], f[14], f[15]);
    P[7] = make_float4(f[16], 1.0f, 0.f, 0.f);

    int txlo = max(mix - rad, 0) >> 2, txhi = min(mix + rad, NVX - 1) >> 2;
    int tylo = max(miy - rad, 0) >> 2, tyhi = min(miy + rad, NVY - 1) >> 2;
    if (txlo > txhi || tylo > tyhi) return;
    for (int tx = txlo; tx <= txhi; tx++)
        for (int ty = tylo; ty <= tyhi; ty++)
            atomicAdd(&g_cnt[tx * NT + ty], 1);
}

// ---------------------------------------------------------------------------
// Scan: exclusive prefix over 2500 tile counts (1 block, 3 tiles/thread)
// ---------------------------------------------------------------------------
__global__ void scan_kernel() {
    __shared__ int s[1024];
    int t = threadIdx.x;
    int b0 = t * 3;
    int c0 = (b0     < N_TILES) ? g_cnt[b0]     : 0;
    int c1 = (b0 + 1 < N_TILES) ? g_cnt[b0 + 1] : 0;
    int c2 = (b0 + 2 < N_TILES) ? g_cnt[b0 + 2] : 0;
    int sum = c0 + c1 + c2;
    s[t] = sum;
    __syncthreads();
    for (int d = 1; d < 1024; d <<= 1) {
        int v = (t >= d) ? s[t - d] : 0;
        __syncthreads();
        s[t] += v;
        __syncthreads();
    }
    int excl = s[t] - sum;
    if (b0     < N_TILES) { g_off[b0]     = excl;           g_cur[b0]     = excl; }
    if (b0 + 1 < N_TILES) { g_off[b0 + 1] = excl + c0;      g_cur[b0 + 1] = excl + c0; }
    if (b0 + 2 < N_TILES) { g_off[b0 + 2] = excl + c0 + c1; g_cur[b0 + 2] = excl + c0 + c1; }
    if (t == 1023) g_off[N_TILES] = s[1023];
}

// ---------------------------------------------------------------------------
// Scatter: insert each gaussian into every overlapped tile's list
// ---------------------------------------------------------------------------
__global__ void scatter_kernel(int n) {
    int g = blockIdx.x * blockDim.x + threadIdx.x;
    if (g >= n) return;
    int sw = g_screen[g];
    int mix = sw & 255, miy = (sw >> 8) & 255, rad = (sw >> 24) & 255;
    int txlo = max(mix - rad, 0) >> 2, txhi = min(mix + rad, NVX - 1) >> 2;
    int tylo = max(miy - rad, 0) >> 2, tyhi = min(miy + rad, NVY - 1) >> 2;
    if (txlo > txhi || tylo > tyhi) return;
    for (int tx = txlo; tx <= txhi; tx++)
        for (int ty = tylo; ty <= tyhi; ty++) {
            int pos = atomicAdd(&g_cur[tx * NT + ty], 1);
            if (pos < LIST_CAP) g_list[pos] = g;
        }
}

// ---------------------------------------------------------------------------
// Packed f32x2 FMA (Blackwell): d = a*b + c per 32-bit half
// ---------------------------------------------------------------------------
__device__ __forceinline__ unsigned long long ffma2(
    unsigned long long a, unsigned long long b, unsigned long long c) {
    unsigned long long d;
    asm("fma.rn.f32x2 %0, %1, %2, %3;" : "=l"(d) : "l"(a), "l"(b), "l"(c));
    return d;
}
__device__ __forceinline__ unsigned long long pack2(float v) {
    unsigned long long d;
    asm("mov.b64 %0, {%1, %1};" : "=l"(d) : "f"(v));
    return d;
}
__device__ __forceinline__ void unpack2(unsigned long long v, float& lo, float& hi) {
    asm("mov.b64 {%0, %1}, %2;" : "=f"(lo), "=f"(hi) : "l"(v));
}

// ---------------------------------------------------------------------------
// Gather: one CTA per 4x4-column tile; thread owns 1 column x 4 z-cells,
// accumulators live entirely in registers (9 packed f32x2 per cell).
// No atomics, no scratch zero/finalize, direct normalized writeout.
// ---------------------------------------------------------------------------
__global__ void __launch_bounds__(64) gather_kernel(float* __restrict__ out) {
    int tile = blockIdx.x;
    int tx = tile / NT, ty = tile % NT;
    int tid = threadIdx.x;
    int col = tid & 15;          // 0..15
    int zq  = tid >> 4;          // 0..3  (warp-uniform per zq pair)
    int ix = tx * TILE_W + (col >> 2);
    int iy = ty * TILE_W + (col & 3);
    int zb = zq * 4;

    float cxf = (float)ix * VOXEL - 39.8f;   // voxel center x
    float cyf = (float)iy * VOXEL - 39.8f;   // voxel center y
    float czf = (float)zb * VOXEL -  0.8f;   // voxel center z (cell j adds j*0.4)

    unsigned long long A[4][9];
    #pragma unroll
    for (int j = 0; j < 4; j++)
        #pragma unroll
        for (int k = 0; k < 9; k++) A[j][k] = 0ull;

    int st = g_off[tile], en = g_off[tile + 1];

    for (int b = st; b < en; b++) {
        int g = g_list[b];                                   // uniform load
        const float4* P = g_par + (size_t)g * 8;
        float4 v0 = P[0];                                    // mx,my,mz,op
        float4 v2 = P[2];                                    // cyz,cxz,sw
        int sw  = __float_as_int(v2.z);
        int mix = sw & 255, miy = (sw >> 8) & 255;
        int miz = (sw >> 16) & 255, rad = (sw >> 24) & 255;

        bool boxxy = (abs(ix - mix) <= rad) && (abs(iy - miy) <= rad);
        bool zany  = (miz + rad >= zb) && (miz - rad <= zb + 3);
        if (!__any_sync(0xffffffffu, boxxy && zany)) continue;

        float4 v1 = P[1];                                    // cxx,cyy,czz,cxy
        float dx = v0.x - cxf, dy = v0.y - cyf;
        float K0 = -0.5f * (v1.x*dx*dx + v1.y*dy*dy) - v1.w*dx*dy;
        float K1 = v2.x*dy + v2.y*dx;                        // cyz*dy + cxz*dx
        float K2 = 0.5f * v1.z;                              // 0.5*czz

        // Feature pairs (9 x u64), pair 8 = (f16, 1.0)
        const ulonglong2* fp = reinterpret_cast<const ulonglong2*>(P + 3);
        ulonglong2 fA = fp[0], fB = fp[1], fC = fp[2], fD = fp[3];
        unsigned long long f8 = fp[4].x;

        #pragma unroll
        for (int j = 0; j < 4; j++) {
            int z = zb + j;
            float dz = v0.z - (czf + (float)j * VOXEL);
            float pw = K0 - dz * (K1 + K2 * dz);
            float c = v0.w * __expf(pw);
            bool pr = boxxy && (z >= miz - rad) && (z <= miz + rad);
            c = pr ? c : 0.f;
            unsigned long long cc = pack2(c);
            A[j][0] = ffma2(cc, fA.x, A[j][0]);
            A[j][1] = ffma2(cc, fA.y, A[j][1]);
            A[j][2] = ffma2(cc, fB.x, A[j][2]);
            A[j][3] = ffma2(cc, fB.y, A[j][3]);
            A[j][4] = ffma2(cc, fC.x, A[j][4]);
            A[j][5] = ffma2(cc, fC.y, A[j][5]);
            A[j][6] = ffma2(cc, fD.x, A[j][6]);
            A[j][7] = ffma2(cc, fD.y, A[j][7]);
            A[j][8] = ffma2(cc, f8,   A[j][8]);
        }
    }

    // Writeout: density + normalized features, straight to d_out
    #pragma unroll
    for (int j = 0; j < 4; j++) {
        int v = (ix * NVY + iy) * NVZ + zb + j;
        float f16a, dens;
        unpack2(A[j][8], f16a, dens);     // (sum c*f16, sum c)
        out[v] = dens;
        float inv = 1.f / fmaxf(dens, 1e-6f);
        float* fo = out + N_VOX + (size_t)v * FEAT_DIM;
        #pragma unroll
        for (int k = 0; k < 8; k++) {
            float lo, hi;
            unpack2(A[j][k], lo, hi);
            fo[2*k]     = lo * inv;
            fo[2*k + 1] = hi * inv;
        }
        fo[16] = f16a * inv;
    }
}

// ---------------------------------------------------------------------------
// Launch
// ---------------------------------------------------------------------------
extern "C" void kernel_launch(void* const* d_in, const int* in_sizes, int n_in,
                              void* d_out, int out_size) {
    const float* means  = (const float*)d_in[0];
    const float* opac   = (const float*)d_in[1];
    const float* scales = (const float*)d_in[2];
    const float* rots   = (const float*)d_in[3];
    const float* feats  = (const float*)d_in[4];
    int n = in_sizes[1];              // opacities: one per gaussian
    if (n > MAXG) n = MAXG;

    zero_cnt_kernel<<<(N_TILES + 255) / 256, 256>>>();
    prep_kernel<<<(n + 255) / 256, 256>>>(means, opac, scales, rots, feats, n);
    scan_kernel<<<1, 1024>>>();
    scatter_kernel<<<(n + 255) / 256, 256>>>(n);
    gather_kernel<<<N_TILES, 64>>>((float*)d_out);
}

// round 11
// speedup vs baseline: 2.3949x; 1.4802x over previous
#include <cuda_runtime.h>

// Problem constants (match reference)
#define NVX 200
#define NVY 200
#define NVZ 16
#define N_VOX (NVX * NVY * NVZ)      // 640000
#define FEAT_DIM 17
#define VOXEL 0.4f

#define TILE_W 4                      // 4x4 columns per tile
#define NT 50                         // 200/4 tiles per axis
#define N_TILES (NT * NT)            // 2500
#define MAXG 16384
#define LIST_CAP 131072

// ---------------------------------------------------------------------------
// Device scratch (static, no allocation)
// Param row: 8 float4 = 32 floats per gaussian:
//   [0] mx,my,mz,op   [1] cxx,cyy,czz,cxy   [2] cyz,cxz,sw,pad
//   [3..6] f0..f15    [7] f16, 1.0, pad, pad
// Feature PAIRS at float offsets (12+2k,13+2k) -> 9 x u64 for fma.rn.f32x2;
// pair 8 = (f16, 1.0) so density (sum of c) accumulates in the high half.
// ---------------------------------------------------------------------------
__device__ float4 g_par[(size_t)MAXG * 8];
__device__ int    g_screen[MAXG];            // packed {mix, miy, miz, rad}
__device__ int    g_cnt[N_TILES];
__device__ int    g_off[N_TILES + 1];
__device__ int    g_cur[N_TILES];
__device__ int    g_list[LIST_CAP];

// ---------------------------------------------------------------------------
__global__ void zero_cnt_kernel() {
    int t = blockIdx.x * blockDim.x + threadIdx.x;
    if (t < N_TILES) g_cnt[t] = 0;
}

// ---------------------------------------------------------------------------
// Prep: derived params + count into every tile the footprint overlaps
// ---------------------------------------------------------------------------
__global__ void prep_kernel(
    const float* __restrict__ means,
    const float* __restrict__ opac,
    const float* __restrict__ scales,
    const float* __restrict__ rots,
    const float* __restrict__ feats,
    int n)
{
    int g = blockIdx.x * blockDim.x + threadIdx.x;
    if (g >= n) return;

    float mx = means[3*g+0], my = means[3*g+1], mz = means[3*g+2];
    float op = opac[g];
    float sx = scales[3*g+0], sy = scales[3*g+1], sz = scales[3*g+2];
    float q0 = rots[4*g+0], q1 = rots[4*g+1], q2 = rots[4*g+2], q3 = rots[4*g+3];

    float qn = rsqrtf(q0*q0 + q1*q1 + q2*q2 + q3*q3 + 1e-8f);
    float r = q0*qn, x = q1*qn, y = q2*qn, z = q3*qn;

    float R00 = 1.f - 2.f*(y*y + z*z);
    float R01 = 2.f*(x*y - r*z);
    float R02 = 2.f*(x*z + r*y);
    float R10 = 2.f*(x*y + r*z);
    float R11 = 1.f - 2.f*(x*x + z*z);
    float R12 = 2.f*(y*z - r*x);
    float R20 = 2.f*(x*z - r*y);
    float R21 = 2.f*(y*z + r*x);
    float R22 = 1.f - 2.f*(x*x + y*y);

    // Cov = R^T diag(s^2) R (R orthogonal)  =>  CovInv = R^T diag(1/s^2) R
    float i0 = 1.f/(sx*sx), i1 = 1.f/(sy*sy), i2 = 1.f/(sz*sz);

    float cxx = R00*R00*i0 + R10*R10*i1 + R20*R20*i2;
    float cyy = R01*R01*i0 + R11*R11*i1 + R21*R21*i2;
    float czz = R02*R02*i0 + R12*R12*i1 + R22*R22*i2;
    float cxy = R00*R01*i0 + R10*R11*i1 + R20*R21*i2;
    float cyz = R01*R02*i0 + R11*R12*i1 + R21*R22*i2;
    float cxz = R00*R02*i0 + R10*R12*i1 + R20*R22*i2;

    float smax = fmaxf(sx, fmaxf(sy, sz));
    int rad = (int)ceilf(smax * 3.0f / VOXEL);
    rad = max(1, min(3, rad));          // offsets limited to +-3 in reference

    int mix = (int)floorf((mx + 40.f) / VOXEL);
    int miy = (int)floorf((my + 40.f) / VOXEL);
    int miz = (int)floorf((mz +  1.f) / VOXEL);

    int sw = (mix & 255) | ((miy & 255) << 8) | ((miz & 255) << 16) | (rad << 24);
    g_screen[g] = sw;

    float4* P = g_par + (size_t)g * 8;
    P[0] = make_float4(mx, my, mz, op);
    P[1] = make_float4(cxx, cyy, czz, cxy);
    P[2] = make_float4(cyz, cxz, __int_as_float(sw), 0.f);
    const float* f = feats + (size_t)FEAT_DIM * g;
    P[3] = make_float4(f[0],  f[1],  f[2],  f[3]);
    P[4] = make_float4(f[4],  f[5],  f[6],  f[7]);
    P[5] = make_float4(f[8],  f[9],  f[10], f[11]);
    P[6] = make_float4(f[12], f[13], f[14], f[15]);
    P[7] = make_float4(f[16], 1.0f, 0.f, 0.f);

    int txlo = max(mix - rad, 0) >> 2, txhi = min(mix + rad, NVX - 1) >> 2;
    int tylo = max(miy - rad, 0) >> 2, tyhi = min(miy + rad, NVY - 1) >> 2;
    if (txlo > txhi || tylo > tyhi) return;
    for (int tx = txlo; tx <= txhi; tx++)
        for (int ty = tylo; ty <= tyhi; ty++)
            atomicAdd(&g_cnt[tx * NT + ty], 1);
}

// ---------------------------------------------------------------------------
// Scan: exclusive prefix over 2500 tile counts (1 block, 3 tiles/thread)
// ---------------------------------------------------------------------------
__global__ void scan_kernel() {
    __shared__ int s[1024];
    int t = threadIdx.x;
    int b0 = t * 3;
    int c0 = (b0     < N_TILES) ? g_cnt[b0]     : 0;
    int c1 = (b0 + 1 < N_TILES) ? g_cnt[b0 + 1] : 0;
    int c2 = (b0 + 2 < N_TILES) ? g_cnt[b0 + 2] : 0;
    int sum = c0 + c1 + c2;
    s[t] = sum;
    __syncthreads();
    for (int d = 1; d < 1024; d <<= 1) {
        int v = (t >= d) ? s[t - d] : 0;
        __syncthreads();
        s[t] += v;
        __syncthreads();
    }
    int excl = s[t] - sum;
    if (b0     < N_TILES) { g_off[b0]     = excl;           g_cur[b0]     = excl; }
    if (b0 + 1 < N_TILES) { g_off[b0 + 1] = excl + c0;      g_cur[b0 + 1] = excl + c0; }
    if (b0 + 2 < N_TILES) { g_off[b0 + 2] = excl + c0 + c1; g_cur[b0 + 2] = excl + c0 + c1; }
    if (t == 1023) g_off[N_TILES] = s[1023];
}

// ---------------------------------------------------------------------------
// Scatter: insert each gaussian into every overlapped tile's list
// ---------------------------------------------------------------------------
__global__ void scatter_kernel(int n) {
    int g = blockIdx.x * blockDim.x + threadIdx.x;
    if (g >= n) return;
    int sw = g_screen[g];
    int mix = sw & 255, miy = (sw >> 8) & 255, rad = (sw >> 24) & 255;
    int txlo = max(mix - rad, 0) >> 2, txhi = min(mix + rad, NVX - 1) >> 2;
    int tylo = max(miy - rad, 0) >> 2, tyhi = min(miy + rad, NVY - 1) >> 2;
    if (txlo > txhi || tylo > tyhi) return;
    for (int tx = txlo; tx <= txhi; tx++)
        for (int ty = tylo; ty <= tyhi; ty++) {
            int pos = atomicAdd(&g_cur[tx * NT + ty], 1);
            if (pos < LIST_CAP) g_list[pos] = g;
        }
}

// ---------------------------------------------------------------------------
// Packed f32x2 FMA (Blackwell): d = a*b + c per 32-bit half
// ---------------------------------------------------------------------------
__device__ __forceinline__ unsigned long long ffma2(
    unsigned long long a, unsigned long long b, unsigned long long c) {
    unsigned long long d;
    asm("fma.rn.f32x2 %0, %1, %2, %3;" : "=l"(d) : "l"(a), "l"(b), "l"(c));
    return d;
}
__device__ __forceinline__ unsigned long long pack2(float v) {
    unsigned long long d;
    asm("mov.b64 %0, {%1, %1};" : "=l"(d) : "f"(v));
    return d;
}
__device__ __forceinline__ void unpack2(unsigned long long v, float& lo, float& hi) {
    asm("mov.b64 {%0, %1}, %2;" : "=f"(lo), "=f"(hi) : "l"(v));
}

// ---------------------------------------------------------------------------
// Gather: one CTA per 4x4-column tile; thread owns 1 column x 4 z-cells,
// accumulators in registers (9 packed f32x2 per cell). Writeout staged
// through smem so global stores are lane-contiguous (coalesced).
// ---------------------------------------------------------------------------
__global__ void __launch_bounds__(64) gather_kernel(float* __restrict__ out) {
    __shared__ float s_feat[256 * FEAT_DIM];   // 17.4 KB, cell-major rows
    __shared__ float s_dens[256];

    int tile = blockIdx.x;
    int tx = tile / NT, ty = tile % NT;
    int tid = threadIdx.x;
    int col = tid & 15;          // 0..15
    int zq  = tid >> 4;          // 0..3
    int ix = tx * TILE_W + (col >> 2);
    int iy = ty * TILE_W + (col & 3);
    int zb = zq * 4;

    float cxf = (float)ix * VOXEL - 39.8f;   // voxel center x
    float cyf = (float)iy * VOXEL - 39.8f;   // voxel center y
    float czf = (float)zb * VOXEL -  0.8f;   // voxel center z (cell j adds j*0.4)

    unsigned long long A[4][9];
    #pragma unroll
    for (int j = 0; j < 4; j++)
        #pragma unroll
        for (int k = 0; k < 9; k++) A[j][k] = 0ull;

    int st = g_off[tile], en = g_off[tile + 1];

    for (int b = st; b < en; b++) {
        int g = g_list[b];                                   // uniform load
        const float4* P = g_par + (size_t)g * 8;
        float4 v0 = P[0];                                    // mx,my,mz,op
        float4 v2 = P[2];                                    // cyz,cxz,sw
        int sw  = __float_as_int(v2.z);
        int mix = sw & 255, miy = (sw >> 8) & 255;
        int miz = (sw >> 16) & 255, rad = (sw >> 24) & 255;

        bool boxxy = (abs(ix - mix) <= rad) && (abs(iy - miy) <= rad);
        bool zany  = (miz + rad >= zb) && (miz - rad <= zb + 3);
        if (!__any_sync(0xffffffffu, boxxy && zany)) continue;

        float4 v1 = P[1];                                    // cxx,cyy,czz,cxy
        float dx = v0.x - cxf, dy = v0.y - cyf;
        float K0 = -0.5f * (v1.x*dx*dx + v1.y*dy*dy) - v1.w*dx*dy;
        float K1 = v2.x*dy + v2.y*dx;                        // cyz*dy + cxz*dx
        float K2 = 0.5f * v1.z;                              // 0.5*czz

        // Feature pairs (9 x u64), pair 8 = (f16, 1.0)
        const ulonglong2* fp = reinterpret_cast<const ulonglong2*>(P + 3);
        ulonglong2 fA = fp[0], fB = fp[1], fC = fp[2], fD = fp[3];
        unsigned long long f8 = fp[4].x;

        #pragma unroll
        for (int j = 0; j < 4; j++) {
            int z = zb + j;
            float dz = v0.z - (czf + (float)j * VOXEL);
            float pw = K0 - dz * (K1 + K2 * dz);
            float c = v0.w * __expf(pw);
            bool pr = boxxy && (z >= miz - rad) && (z <= miz + rad);
            c = pr ? c : 0.f;
            unsigned long long cc = pack2(c);
            A[j][0] = ffma2(cc, fA.x, A[j][0]);
            A[j][1] = ffma2(cc, fA.y, A[j][1]);
            A[j][2] = ffma2(cc, fB.x, A[j][2]);
            A[j][3] = ffma2(cc, fB.y, A[j][3]);
            A[j][4] = ffma2(cc, fC.x, A[j][4]);
            A[j][5] = ffma2(cc, fC.y, A[j][5]);
            A[j][6] = ffma2(cc, fD.x, A[j][6]);
            A[j][7] = ffma2(cc, fD.y, A[j][7]);
            A[j][8] = ffma2(cc, f8,   A[j][8]);
        }
    }

    // ---- Stage normalized results into smem (cell-major 17-float rows) ----
    #pragma unroll
    for (int j = 0; j < 4; j++) {
        int cell = col * 16 + zb + j;     // == (cx*4+cy)*16 + iz
        float f16a, dens;
        unpack2(A[j][8], f16a, dens);     // (sum c*f16, sum c)
        s_dens[cell] = dens;
        float inv = 1.f / fmaxf(dens, 1e-6f);
        float* sf = s_feat + cell * FEAT_DIM;
        #pragma unroll
        for (int k = 0; k < 8; k++) {
            float lo, hi;
            unpack2(A[j][k], lo, hi);
            sf[2*k]     = lo * inv;
            sf[2*k + 1] = hi * inv;
        }
        sf[16] = f16a * inv;
    }
    __syncthreads();

    // ---- Coalesced writeout: 4 contiguous segments (one per ix row) ----
    int X0 = tx * TILE_W, Y0 = ty * TILE_W;
    #pragma unroll
    for (int cx = 0; cx < 4; cx++) {
        int v0 = ((X0 + cx) * NVY + Y0) * NVZ;        // 64 consecutive voxels
        out[v0 + tid] = s_dens[cx * 64 + tid];        // blockDim == 64
        const float* src = s_feat + cx * 64 * FEAT_DIM;
        float* dst = out + N_VOX + (size_t)v0 * FEAT_DIM;
        for (int i = tid; i < 64 * FEAT_DIM; i += 64) dst[i] = src[i];
    }
}

// ---------------------------------------------------------------------------
// Launch
// ---------------------------------------------------------------------------
extern "C" void kernel_launch(void* const* d_in, const int* in_sizes, int n_in,
                              void* d_out, int out_size) {
    const float* means  = (const float*)d_in[0];
    const float* opac   = (const float*)d_in[1];
    const float* scales = (const float*)d_in[2];
    const float* rots   = (const float*)d_in[3];
    const float* feats  = (const float*)d_in[4];
    int n = in_sizes[1];              // opacities: one per gaussian
    if (n > MAXG) n = MAXG;

    zero_cnt_kernel<<<(N_TILES + 255) / 256, 256>>>();
    prep_kernel<<<(n + 255) / 256, 256>>>(means, opac, scales, rots, feats, n);
    scan_kernel<<<1, 1024>>>();
    scatter_kernel<<<(n + 127) / 128, 128>>>(n);
    gather_kernel<<<N_TILES, 64>>>((float*)d_out);
}